// round 12
// baseline (speedup 1.0000x reference)
#include <cuda_runtime.h>
#include <math.h>

#define TPB 256

// Prologue-computed operands (k-major [k][out])
__device__ float g_P[128*128];   // (Wq^T Wk)/sqrt(d)
__device__ float g_G[128*128];   // Wv^T Theta^T
__device__ float g_U[128*64];    // [k][j]: j<32 -> (W1q@Wq)[j,k], j>=32 -> (W1k@Wk)[j-32,k]

typedef unsigned long long u64;

__device__ __forceinline__ float4 ld4(const float* p){ return *reinterpret_cast<const float4*>(p); }
__device__ __forceinline__ void st4(float* p, float4 v){ *reinterpret_cast<float4*>(p)=v; }
__device__ __forceinline__ u64 ldu(const float* p){ return *reinterpret_cast<const u64*>(p); }
__device__ __forceinline__ void stu(float* p, u64 v){ *reinterpret_cast<u64*>(p)=v; }
__device__ __forceinline__ ulonglong2 ldp2(const float* p){ return *reinterpret_cast<const ulonglong2*>(p); }
__device__ __forceinline__ void stp2(float* p, u64 a, u64 b){
    ulonglong2 v; v.x = a; v.y = b;
    *reinterpret_cast<ulonglong2*>(p) = v;
}
__device__ __forceinline__ u64 pk2(float x, float y){ u64 r; asm("mov.b64 %0,{%1,%2};":"=l"(r):"f"(x),"f"(y)); return r; }
__device__ __forceinline__ float2 upk2(u64 v){ float2 f; asm("mov.b64 {%0,%1},%2;":"=f"(f.x),"=f"(f.y):"l"(v)); return f; }
__device__ __forceinline__ u64 fma2(u64 a,u64 b,u64 c){ u64 d; asm("fma.rn.f32x2 %0,%1,%2,%3;":"=l"(d):"l"(a),"l"(b),"l"(c)); return d; }
__device__ __forceinline__ u64 add2(u64 a,u64 b){ u64 d; asm("add.rn.f32x2 %0,%1,%2;":"=l"(d):"l"(a),"l"(b)); return d; }

// swizzled address of 16B block `blk` in row `row` of a [32][128] tile
__device__ __forceinline__ int swz(int row, int blk){ return row*128 + ((blk ^ ((row>>2)&7)) << 2); }

// ---------------- fast prep (unchanged, measured ~3us) ----------------
__global__ void prep_kernel(const float* __restrict__ Wq, const float* __restrict__ Wk,
                            const float* __restrict__ Wv, const float* __restrict__ Th,
                            const float* __restrict__ W1)
{
    const int bx = blockIdx.x, tid = threadIdx.x;
    if (bx < 128) {
        const int d = bx, k = tid;
        float accP = 0.f, accG = 0.f;
#pragma unroll 8
        for (int i = 0; i < 128; i++) {
            accP = fmaf(Wq[i*128 + k], Wk[i*128 + d], accP);
            accG = fmaf(Wv[i*128 + k], Th[d*128 + i], accG);
        }
        g_P[k*128 + d] = accP * 0.08838834764831845f;
        g_G[k*128 + d] = accG;
    } else {
        const int j = bx - 128, k = tid;
        const float* w1row = (j < 32) ? (W1 + j*260) : (W1 + (j-32)*260 + 128);
        const float* wc    = (j < 32) ? Wq : Wk;
        float acc = 0.f;
#pragma unroll 8
        for (int d = 0; d < 128; d++) acc = fmaf(w1row[d], wc[d*128 + k], acc);
        g_U[k*64 + j] = acc;
    }
}

// -------- shared memory layout (float offsets) --------
#define OZ    0         // Z [32][128] SWIZZLED = 4096     (persistent)
#define OC    4096      // C1 -> AZ -> y [32][128] SWIZZLED = 4096
#define OST   8192      // 4224: staging 2buf x [16][128]=4096 | ZTP u64[64][33]=4224 | HQ[32][36]@+0, HKT[32][33]@+1152
#define OSB   12416     // b1@0, W2@32, mask@64, consts@96, W1e@128 (256)
#define OW    12672     // LOG [32][36] = 1152
#define SMEMF 13824     // 55296 bytes -> 4 CTAs/SM

// dst[32x128](swz) = sIn[32x128](swz) @ gW[128][128] (+resid(swz)).
// 256 threads: warp w owns cols w*16..+15; lane(lg,lc) = rows lg*4..+3 x cols w*16+lc*4..+3.
// Register-prefetch weight pipeline, ONE __syncthreads per tile.
__device__ __forceinline__ void gemm_big(const float* __restrict__ sIn,
                                         const float* __restrict__ gW,
                                         float* sStage, float* dst,
                                         const float* resid, int tid)
{
    const int warp = tid >> 5, lane = tid & 31;
    const int lg = lane >> 2, lc = lane & 3;
    const int cw = warp*16 + lc*4;            // col base
    const int oblk = (warp*4 + lc) ^ lg;      // swizzled out block
    const int off0 = tid * 4;                 // float4 #tid in [16][128] tile
    const int off1 = off0 + 1024;
    const int kr0 = off0 >> 7, cc0 = off0 & 127;
    const int kr1 = off1 >> 7, cc1 = off1 & 127;

    u64 acc[8];                               // [row 0..3][colpair 0..1]
#pragma unroll
    for (int i = 0; i < 8; i++) acc[i] = 0ull;

    // prologue: tile 0 -> buf 0 (LDG -> regs -> STS)
    float4 p0 = ld4(gW + kr0*128 + cc0);
    float4 p1 = ld4(gW + kr1*128 + cc1);
    st4(sStage + off0, p0);
    st4(sStage + off1, p1);
    __syncthreads();

    for (int kt = 0; kt < 8; kt++) {
        const int buf = kt & 1;
        if (kt < 7) {           // prefetch next tile into registers (hidden by compute)
            const int kb = (kt + 1) * 16;
            p0 = ld4(gW + (kb + kr0)*128 + cc0);
            p1 = ld4(gW + (kb + kr1)*128 + cc1);
        }
        const float* w = sStage + buf * 2048;
#pragma unroll
        for (int kk = 0; kk < 16; kk += 4) {
            const int zb = (((kt*16 + kk) >> 2) ^ lg) << 2;   // swizzled z block offset
            float4 z[4];
#pragma unroll
            for (int i = 0; i < 4; i++) z[i] = ld4(sIn + (lg*4 + i)*128 + zb);
#pragma unroll
            for (int u = 0; u < 4; u++) {
                ulonglong2 wv = ldp2(w + (kk+u)*128 + cw);
#pragma unroll
                for (int i = 0; i < 4; i++) {
                    float a = (u==0) ? z[i].x : (u==1) ? z[i].y : (u==2) ? z[i].z : z[i].w;
                    u64 ad = pk2(a, a);
                    acc[i*2]   = fma2(ad, wv.x, acc[i*2]);
                    acc[i*2+1] = fma2(ad, wv.y, acc[i*2+1]);
                }
            }
        }
        if (kt < 7) {           // registers -> other buffer
            float* sd = sStage + (buf ^ 1) * 2048;
            st4(sd + off0, p0);
            st4(sd + off1, p1);
            __syncthreads();
        }
    }
    __syncthreads();            // all compute done before stores / staging reuse
#pragma unroll
    for (int i = 0; i < 4; i++) {
        const int base = (lg*4 + i)*128 + oblk*4;
        u64 o0 = acc[i*2], o1 = acc[i*2+1];
        if (resid) {
            ulonglong2 r = ldp2(resid + base);
            o0 = add2(o0, r.x);
            o1 = add2(o1, r.y);
        }
        stp2(dst + base, o0, o1);
    }
}

__global__ __launch_bounds__(TPB, 4)
void fused_gnn_kernel(const float* __restrict__ x, const float* __restrict__ edge,
                      const float* __restrict__ Aprior, const unsigned char* __restrict__ pmask,
                      const float* __restrict__ Wfuse, const float* __restrict__ W1,
                      const float* __restrict__ b1g, const float* __restrict__ W2g,
                      const float* __restrict__ b2g, const float* __restrict__ gammag,
                      const float* __restrict__ betag, const float* __restrict__ physw,
                      const float* __restrict__ priorw, float* __restrict__ out)
{
    extern __shared__ float sm[];
    const int tid = threadIdx.x;
    const int bt = blockIdx.x;
    const int b = bt >> 6, t = bt & 63;
    const int warp = tid >> 5, lane = tid & 31;

    // ---------------- Phase 0: stage Z (swizzled) + small tensors ----------------
#pragma unroll
    for (int it = 0; it < 4; it++) {
        int idx = tid + it * TPB;              // idx = n*32 + dgroup
        int n = idx >> 5, dg = idx & 31;
        st4(sm + OZ + swz(n, dg), ld4(x + ((((size_t)b*32 + n)*64 + t)*128) + dg*4));
    }
    if (tid < 32) {
        sm[OSB + tid]      = b1g[tid];
        sm[OSB + 32 + tid] = W2g[tid];
        sm[OSB + 64 + tid] = pmask[b*32 + tid] ? 1.f : 0.f;
        if (tid == 0) { sm[OSB+96] = physw[0]; sm[OSB+97] = priorw[0]; sm[OSB+98] = b2g[0]; }
    }
    if (tid >= 64 && tid < 192) {              // W1e [j][e]
        int i = tid - 64;
        sm[OSB + 128 + i] = W1[(i>>2)*260 + 256 + (i&3)];
    }
    __syncthreads();

    // ---------------- Phase 1: C1 = Z @ P -> OC (swizzled) ----------------
    gemm_big(sm + OZ, g_P, sm + OST, sm + OC, nullptr, tid);

    // ---------------- Phase 2a: build packed Z^T (ZTP u64[64][33]) in OST ----------------
#pragma unroll
    for (int it = 0; it < 4; it++) {
        int idx = tid + it * TPB;
        int n = idx >> 5, dg = idx & 31;
        float4 v = ld4(sm + OZ + swz(n, dg));
        stu(sm + OST + (dg*2 + 0)*66 + n*2, pk2(v.x, v.y));
        stu(sm + OST + (dg*2 + 1)*66 + n*2, pk2(v.z, v.w));
    }
    __syncthreads();

    // ---------------- Phase 2b: content = C1 @ Z^T -> LOG ----------------
    {
        u64 acc2[4] = {0ull, 0ull, 0ull, 0ull};
        for (int k = 0; k < 128; k += 4) {
            u64 zt01 = ldu(sm + OST + k*33      + lane*2);   // (k/2)*66 = k*33
            u64 zt23 = ldu(sm + OST + k*33 + 66 + lane*2);
#pragma unroll
            for (int i = 0; i < 4; i++) {
                ulonglong2 c2 = ldp2(sm + OC + swz(warp*4 + i, k >> 2));
                acc2[i] = fma2(c2.x, zt01, acc2[i]);
                acc2[i] = fma2(c2.y, zt23, acc2[i]);
            }
        }
#pragma unroll
        for (int i = 0; i < 4; i++) {
            float2 f = upk2(acc2[i]);
            sm[OW + (warp*4+i)*36 + lane] = f.x + f.y;
        }
    }
    __syncthreads();   // ZTP reads done -> OST reusable for HQ/HKT

    // ---------------- Phase 4: H = Z @ gU (hq | hk) -- warp=4 rows, lane=j-pair ----------------
    {
        const int r0 = warp * 4;
        const int j2 = lane * 2;
        u64 acc4[4] = {0ull, 0ull, 0ull, 0ull};
#pragma unroll 4
        for (int k = 0; k < 128; k += 4) {
            u64 wr[4];
#pragma unroll
            for (int u = 0; u < 4; u++) wr[u] = ldu(&g_U[(k+u)*64 + j2]);
            const int zb = ((k >> 2) ^ (warp & 7)) << 2;
            float4 z[4];
#pragma unroll
            for (int i = 0; i < 4; i++) z[i] = ld4(sm + OZ + (r0 + i)*128 + zb);
#pragma unroll
            for (int u = 0; u < 4; u++) {
#pragma unroll
                for (int i = 0; i < 4; i++) {
                    float a = (u==0) ? z[i].x : (u==1) ? z[i].y : (u==2) ? z[i].z : z[i].w;
                    acc4[i] = fma2(pk2(a, a), wr[u], acc4[i]);
                }
            }
        }
#pragma unroll
        for (int i = 0; i < 4; i++) {
            int n = r0 + i;
            if (j2 < 32) {                       // hq -> HQ[32][36] @ OST
                stu(sm + OST + n*36 + j2, acc4[i]);
            } else {                             // hk -> HKT[j][n] [32][33] @ OST+1152
                float2 f = upk2(acc4[i]);
                int j = j2 - 32;
                sm[OST + 1152 + (j+0)*33 + n] = f.x;
                sm[OST + 1152 + (j+1)*33 + n] = f.y;
            }
        }
    }

    // ---------------- Prefetch edge / prior ----------------
    const int pn = tid >> 3, pm0 = (tid & 7) << 2;
    float4 e4[4]; float lpr[4];
    {
        const float wf0 = __ldg(Wfuse+0), wf1 = __ldg(Wfuse+1), wf2 = __ldg(Wfuse+2),
                    wf3 = __ldg(Wfuse+3), wf4 = __ldg(Wfuse+4);
#pragma unroll
        for (int mm = 0; mm < 4; mm++) {
            size_t pair = (size_t)bt*1024 + pn*32 + pm0 + mm;
            e4[mm] = ld4(edge + pair*4);
            const float* ap = Aprior + pair*5;
            float p = ap[0]*wf0 + ap[1]*wf1 + ap[2]*wf2 + ap[3]*wf3 + ap[4]*wf4;
            if (!isfinite(p)) p = 0.f;
            p = fmaxf(p, 0.f);
            lpr[mm] = logf(p + 1e-6f);
        }
    }
    __syncthreads();

    // ---------------- Phase 5: phys MLP + prior + logits ----------------
    {
        float ph[4] = {0.f, 0.f, 0.f, 0.f};
#pragma unroll
        for (int j = 0; j < 32; j += 4) {
            float4 hqv = ld4(sm + OST + pn*36 + j);
            float4 b1v = ld4(sm + OSB + j);
            float4 w2v = ld4(sm + OSB + 32 + j);
            float hq4[4] = {hqv.x, hqv.y, hqv.z, hqv.w};
            float b14[4] = {b1v.x, b1v.y, b1v.z, b1v.w};
            float w24[4] = {w2v.x, w2v.y, w2v.z, w2v.w};
#pragma unroll
            for (int jj = 0; jj < 4; jj++) {
                int jc = j + jj;
                float hqb = hq4[jj] + b14[jj];
                float w2s = w24[jj];
                float4 we = ld4(sm + OSB + 128 + jc*4);
#pragma unroll
                for (int mm = 0; mm < 4; mm++) {
                    float h = hqb + sm[OST + 1152 + jc*33 + pm0 + mm]
                            + e4[mm].x*we.x + e4[mm].y*we.y
                            + e4[mm].z*we.z + e4[mm].w*we.w;
                    h = fmaxf(h, 0.f);
                    ph[mm] = fmaf(h, w2s, ph[mm]);
                }
            }
        }
        float pw = sm[OSB+96], prw = sm[OSB+97], b2v = sm[OSB+98];
        float mn = sm[OSB + 64 + pn];
#pragma unroll
        for (int mm = 0; mm < 4; mm++) {
            float lg = sm[OW + pn*36 + pm0 + mm]
                     + pw * (ph[mm] + b2v)
                     + prw * lpr[mm];
            if (mn != 0.f || sm[OSB + 64 + pm0 + mm] != 0.f) lg = -1e9f;
            sm[OW + pn*36 + pm0 + mm] = lg;
        }
    }
    __syncthreads();

    // ---------------- Phase 6: softmax (warp per 4 rows) ----------------
#pragma unroll
    for (int q = 0; q < 4; q++) {
        int n = warp*4 + q;
        float v = sm[OW + n*36 + lane];
        float mx = v;
#pragma unroll
        for (int off = 16; off > 0; off >>= 1)
            mx = fmaxf(mx, __shfl_xor_sync(0xffffffffu, mx, off));
        float e = expf(v - mx);
        float s = e;
#pragma unroll
        for (int off = 16; off > 0; off >>= 1)
            s += __shfl_xor_sync(0xffffffffu, s, off);
        sm[OW + n*36 + lane] = e / s;
    }
    __syncthreads();

    // ---------------- Phase 7: AZ = alpha @ Z -> OC (swizzled) ----------------
    {
        const int r0 = warp * 4;
        u64 acc[8];
#pragma unroll
        for (int i = 0; i < 8; i++) acc[i] = 0ull;
#pragma unroll 2
        for (int k = 0; k < 32; k += 4) {
            float4 a[4];
#pragma unroll
            for (int i = 0; i < 4; i++) a[i] = ld4(sm + OW + (r0 + i)*36 + k);
#pragma unroll
            for (int u = 0; u < 4; u++) {
                ulonglong2 zv = ldp2(sm + OZ + swz(k + u, lane));
#pragma unroll
                for (int i = 0; i < 4; i++) {
                    float av = (u==0) ? a[i].x : (u==1) ? a[i].y : (u==2) ? a[i].z : a[i].w;
                    u64 ad = pk2(av, av);
                    acc[i*2]   = fma2(ad, zv.x, acc[i*2]);
                    acc[i*2+1] = fma2(ad, zv.y, acc[i*2+1]);
                }
            }
        }
        __syncthreads();   // C1 in OC fully consumed (phase 2)
#pragma unroll
        for (int i = 0; i < 4; i++)
            stp2(sm + OC + swz(r0 + i, lane), acc[i*2], acc[i*2+1]);
    }
    __syncthreads();

    // ---------------- Phase 8: y = Z + AZ @ G -> OC (in-place, swizzled) ----------------
    gemm_big(sm + OC, g_G, sm + OST, sm + OC, sm + OZ, tid);
    __syncthreads();

    // ---------------- Phase 9: LayerNorm + masked store ----------------
    {
        float4 gv = __ldg(reinterpret_cast<const float4*>(gammag + lane*4));
        float4 bv = __ldg(reinterpret_cast<const float4*>(betag + lane*4));
#pragma unroll
        for (int q = 0; q < 4; q++) {
            int n = warp*4 + q;
            float4 y = ld4(sm + OC + swz(n, lane));
            float s  = y.x + y.y + y.z + y.w;
            float s2 = y.x*y.x + y.y*y.y + y.z*y.z + y.w*y.w;
#pragma unroll
            for (int off = 16; off > 0; off >>= 1) {
                s  += __shfl_xor_sync(0xffffffffu, s, off);
                s2 += __shfl_xor_sync(0xffffffffu, s2, off);
            }
            float mu   = s * (1.f/128.f);
            float var  = s2 * (1.f/128.f) - mu*mu;
            float rstd = rsqrtf(var + 1e-5f);
            float4 o;
            o.x = (y.x - mu)*rstd*gv.x + bv.x;
            o.y = (y.y - mu)*rstd*gv.y + bv.y;
            o.z = (y.z - mu)*rstd*gv.z + bv.z;
            o.w = (y.w - mu)*rstd*gv.w + bv.w;
            if (sm[OSB + 64 + n] != 0.f) o = make_float4(0.f, 0.f, 0.f, 0.f);
            reinterpret_cast<float4*>(out)[(((size_t)b*32 + n)*64 + t)*32 + lane] = o;
        }
    }
}

extern "C" void kernel_launch(void* const* d_in, const int* in_sizes, int n_in,
                              void* d_out, int out_size) {
    (void)in_sizes; (void)n_in; (void)out_size;
    const float* x      = (const float*)d_in[0];
    const float* edge   = (const float*)d_in[1];
    const float* Aprior = (const float*)d_in[2];
    const unsigned char* pmask = (const unsigned char*)d_in[3];
    const float* Wq     = (const float*)d_in[4];
    const float* Wk     = (const float*)d_in[5];
    const float* Wv     = (const float*)d_in[6];
    const float* Th     = (const float*)d_in[7];
    const float* Wfuse  = (const float*)d_in[8];
    const float* W1     = (const float*)d_in[9];
    const float* b1     = (const float*)d_in[10];
    const float* W2     = (const float*)d_in[11];
    const float* b2     = (const float*)d_in[12];
    const float* gamma  = (const float*)d_in[13];
    const float* beta   = (const float*)d_in[14];
    const float* physw  = (const float*)d_in[15];
    const float* priorw = (const float*)d_in[16];
    float* out = (float*)d_out;

    prep_kernel<<<192, 128>>>(Wq, Wk, Wv, Th, W1);

    cudaFuncSetAttribute(fused_gnn_kernel,
                         cudaFuncAttributeMaxDynamicSharedMemorySize, SMEMF * 4);
    fused_gnn_kernel<<<512, TPB, SMEMF * 4>>>(x, edge, Aprior, pmask, Wfuse, W1, b1, W2, b2,
                                              gamma, beta, physw, priorw, out);
}

// round 13
// speedup vs baseline: 1.3079x; 1.3079x over previous
#include <cuda_runtime.h>
#include <cuda_bf16.h>
#include <math.h>

#define TPB 256

typedef unsigned long long u64;
typedef unsigned int u32;

// Prologue-computed operands
__device__ float g_U[128*64];        // [k][j] for H-GEMM
// bf16 hi/lo fragment-packed B for P and G:
// u32 index = ((ks*16 + nt)*32 + lane)*2 + breg ; u16 half = kin&1
__device__ u32 g_Pbh[8*16*32*2];
__device__ u32 g_Pbl[8*16*32*2];
__device__ u32 g_Gbh[8*16*32*2];
__device__ u32 g_Gbl[8*16*32*2];

__device__ __forceinline__ float4 ld4(const float* p){ return *reinterpret_cast<const float4*>(p); }
__device__ __forceinline__ void st4(float* p, float4 v){ *reinterpret_cast<float4*>(p)=v; }
__device__ __forceinline__ u64 ldu(const float* p){ return *reinterpret_cast<const u64*>(p); }
__device__ __forceinline__ void stu(float* p, u64 v){ *reinterpret_cast<u64*>(p)=v; }
__device__ __forceinline__ ulonglong2 ldp2(const float* p){ return *reinterpret_cast<const ulonglong2*>(p); }
__device__ __forceinline__ void stp2(float* p, u64 a, u64 b){
    ulonglong2 v; v.x = a; v.y = b; *reinterpret_cast<ulonglong2*>(p) = v;
}
__device__ __forceinline__ u64 pk2(float x, float y){ u64 r; asm("mov.b64 %0,{%1,%2};":"=l"(r):"f"(x),"f"(y)); return r; }
__device__ __forceinline__ float2 upk2(u64 v){ float2 f; asm("mov.b64 {%0,%1},%2;":"=f"(f.x),"=f"(f.y):"l"(v)); return f; }
__device__ __forceinline__ u64 fma2(u64 a,u64 b,u64 c){ u64 d; asm("fma.rn.f32x2 %0,%1,%2,%3;":"=l"(d):"l"(a),"l"(b),"l"(c)); return d; }
__device__ __forceinline__ u64 add2(u64 a,u64 b){ u64 d; asm("add.rn.f32x2 %0,%1,%2;":"=l"(d):"l"(a),"l"(b)); return d; }

__device__ __forceinline__ void mma16816(float* c, const u32* a, u32 b0, u32 b1){
    asm("mma.sync.aligned.m16n8k16.row.col.f32.bf16.bf16.f32 "
        "{%0,%1,%2,%3},{%4,%5,%6,%7},{%8,%9},{%0,%1,%2,%3};"
        : "+f"(c[0]),"+f"(c[1]),"+f"(c[2]),"+f"(c[3])
        : "r"(a[0]),"r"(a[1]),"r"(a[2]),"r"(a[3]),"r"(b0),"r"(b1));
}
__device__ __forceinline__ void ldsm4(u32* r, u32 addr){
    asm volatile("ldmatrix.sync.aligned.m8n8.x4.shared.b16 {%0,%1,%2,%3},[%4];"
        : "=r"(r[0]),"=r"(r[1]),"=r"(r[2]),"=r"(r[3]) : "r"(addr));
}
__device__ __forceinline__ u32 bf2pk(float hi_src, float lo_src){  // pack {hi=hi_src? no: upper=arg1}
    u32 r; asm("cvt.rn.satfinite.bf16x2.f32 %0,%1,%2;" : "=r"(r) : "f"(hi_src), "f"(lo_src)); return r;
}

// ---------------- prep ----------------
// blocks 0..127: d = bx, k = tid: P[k][d], G[k][d] -> bf16 hi/lo frag arrays (u16 scatter)
// blocks 128..191: j = bx-128, k = tid: gU[k][j]
__global__ void prep_kernel(const float* __restrict__ Wq, const float* __restrict__ Wk,
                            const float* __restrict__ Wv, const float* __restrict__ Th,
                            const float* __restrict__ W1)
{
    const int bx = blockIdx.x, tid = threadIdx.x;
    if (bx < 128) {
        const int d = bx, k = tid;
        float accP = 0.f, accG = 0.f;
#pragma unroll 8
        for (int i = 0; i < 128; i++) {
            accP = fmaf(Wq[i*128 + k], Wk[i*128 + d], accP);
            accG = fmaf(Wv[i*128 + k], Th[d*128 + i], accG);
        }
        accP *= 0.08838834764831845f;
        const int ks = k >> 4, kin = k & 15;
        const int breg = kin >> 3, rem = kin & 7, tq = rem >> 1, half = rem & 1;
        const int nt = d >> 3, g = d & 7, ln = g*4 + tq;
        const int u16i = (((ks*16 + nt)*32 + ln)*2 + breg)*2 + half;

        unsigned short ph, pl, gh, gl;
        asm("cvt.rn.bf16.f32 %0,%1;" : "=h"(ph) : "f"(accP));
        float phf = __uint_as_float(((u32)ph) << 16);
        asm("cvt.rn.bf16.f32 %0,%1;" : "=h"(pl) : "f"(accP - phf));
        asm("cvt.rn.bf16.f32 %0,%1;" : "=h"(gh) : "f"(accG));
        float ghf = __uint_as_float(((u32)gh) << 16);
        asm("cvt.rn.bf16.f32 %0,%1;" : "=h"(gl) : "f"(accG - ghf));
        reinterpret_cast<unsigned short*>(g_Pbh)[u16i] = ph;
        reinterpret_cast<unsigned short*>(g_Pbl)[u16i] = pl;
        reinterpret_cast<unsigned short*>(g_Gbh)[u16i] = gh;
        reinterpret_cast<unsigned short*>(g_Gbl)[u16i] = gl;
    } else {
        const int j = bx - 128, k = tid;
        const float* w1row = (j < 32) ? (W1 + j*260) : (W1 + (j-32)*260 + 128);
        const float* wc    = (j < 32) ? Wq : Wk;
        float acc = 0.f;
#pragma unroll 8
        for (int d = 0; d < 128; d++) acc = fmaf(w1row[d], wc[d*128 + k], acc);
        g_U[k*64 + j] = acc;
    }
}

// -------- shared memory layout (float offsets) --------
#define OZ    0         // Z [32][136] = 4352 (persistent)
#define OC    4352      // C1 -> AZ -> y [32][136] = 4352
#define OSCR  8704      // 4224: Zbf/AZbf hi[2048]+lo[2048] | ZTP u64[64][33]=4224 | HQ[32][36]@+0, HKT[32][33]@+1152
#define OSB   12928     // b1@0, W2@32, mask@64, consts@96, W1e@128 (256)
#define OW    13184     // LOG [32][36] = 1152
#define SMEMF 14336     // 57344 bytes -> 4 CTAs/SM

// Convert src[32][136] fp32 -> bf16 hi/lo tiles at sDst (hi @+0, lo @+2048 floats),
// row n = 64 floats (128 bf16), 16B blocks XOR-swizzled by (n&7).
__device__ __forceinline__ void cvt_split(const float* __restrict__ src, float* sDst, int tid){
    const int n = tid >> 3, cblk = tid & 7;
    const float* sp = src + n*136 + cblk*16;
    u32 hi[8], lo[8];
#pragma unroll
    for (int i = 0; i < 4; i++){
        float4 v = ld4(sp + i*4);
        u32 h0 = bf2pk(v.y, v.x);
        float hx = __uint_as_float(h0 << 16), hy = __uint_as_float(h0 & 0xffff0000u);
        u32 l0 = bf2pk(v.y - hy, v.x - hx);
        u32 h1 = bf2pk(v.w, v.z);
        float hz = __uint_as_float(h1 << 16), hw = __uint_as_float(h1 & 0xffff0000u);
        u32 l1 = bf2pk(v.w - hw, v.z - hz);
        hi[i*2] = h0; hi[i*2+1] = h1; lo[i*2] = l0; lo[i*2+1] = l1;
    }
    const int b0 = (cblk*2) ^ (n & 7), b1 = (cblk*2 + 1) ^ (n & 7);
    st4(sDst + n*64 + b0*4, make_float4(__uint_as_float(hi[0]), __uint_as_float(hi[1]),
                                        __uint_as_float(hi[2]), __uint_as_float(hi[3])));
    st4(sDst + n*64 + b1*4, make_float4(__uint_as_float(hi[4]), __uint_as_float(hi[5]),
                                        __uint_as_float(hi[6]), __uint_as_float(hi[7])));
    st4(sDst + 2048 + n*64 + b0*4, make_float4(__uint_as_float(lo[0]), __uint_as_float(lo[1]),
                                               __uint_as_float(lo[2]), __uint_as_float(lo[3])));
    st4(sDst + 2048 + n*64 + b1*4, make_float4(__uint_as_float(lo[4]), __uint_as_float(lo[5]),
                                               __uint_as_float(lo[6]), __uint_as_float(lo[7])));
}

// D[32][136] = A(bf16 split tiles in smem) @ B(frag-packed global) (+resid[32][136])
// warp: mtile mw=warp&1 (rows mw*16..+15), n-group ntg=warp>>1 (cols ntg*32..+31).
__device__ __forceinline__ void gemm_mma(const float* __restrict__ sAbf,
                                         const u32* __restrict__ Bh, const u32* __restrict__ Bl,
                                         float* dst, const float* resid, int tid)
{
    const int warp = tid >> 5, lane = tid & 31;
    const int mw = warp & 1, ntg = warp >> 1;
    const int m = mw*16 + (lane & 7) + ((lane >> 3) & 1)*8;   // ldmatrix row for this lane
    const int kbh = lane >> 4;                                 // +8-col half select
    const u32 base = (u32)__cvta_generic_to_shared(sAbf);

    float c[4][4];
#pragma unroll
    for (int nt = 0; nt < 4; nt++){ c[nt][0]=0.f; c[nt][1]=0.f; c[nt][2]=0.f; c[nt][3]=0.f; }

#pragma unroll
    for (int ks = 0; ks < 8; ks++){
        const int kb = ks*2 + kbh;
        const u32 off = (u32)(m*256 + ((kb ^ (m & 7)) << 4));
        u32 ah[4], al[4];
        ldsm4(ah, base + off);
        ldsm4(al, base + 8192 + off);
        const u32* bhp = Bh + ((ks*16 + ntg*4)*32 + lane)*2;
        const u32* blp = Bl + ((ks*16 + ntg*4)*32 + lane)*2;
#pragma unroll
        for (int nt = 0; nt < 4; nt++){
            uint2 bh = *reinterpret_cast<const uint2*>(bhp + nt*64);
            uint2 bl = *reinterpret_cast<const uint2*>(blp + nt*64);
            mma16816(c[nt], ah, bh.x, bh.y);
            mma16816(c[nt], ah, bl.x, bl.y);
            mma16816(c[nt], al, bh.x, bh.y);
        }
    }
    const int r0 = mw*16 + (lane >> 2), r1 = r0 + 8;
    const int cb = ntg*32 + (lane & 3)*2;
#pragma unroll
    for (int nt = 0; nt < 4; nt++){
        const int col = cb + nt*8;
        float2 v0 = make_float2(c[nt][0], c[nt][1]);
        float2 v1 = make_float2(c[nt][2], c[nt][3]);
        if (resid){
            float2 z0 = *reinterpret_cast<const float2*>(resid + r0*136 + col);
            float2 z1 = *reinterpret_cast<const float2*>(resid + r1*136 + col);
            v0.x += z0.x; v0.y += z0.y; v1.x += z1.x; v1.y += z1.y;
        }
        *reinterpret_cast<float2*>(dst + r0*136 + col) = v0;
        *reinterpret_cast<float2*>(dst + r1*136 + col) = v1;
    }
}

__global__ __launch_bounds__(TPB, 4)
void fused_gnn_kernel(const float* __restrict__ x, const float* __restrict__ edge,
                      const float* __restrict__ Aprior, const unsigned char* __restrict__ pmask,
                      const float* __restrict__ Wfuse, const float* __restrict__ W1,
                      const float* __restrict__ b1g, const float* __restrict__ W2g,
                      const float* __restrict__ b2g, const float* __restrict__ gammag,
                      const float* __restrict__ betag, const float* __restrict__ physw,
                      const float* __restrict__ priorw, float* __restrict__ out)
{
    extern __shared__ float sm[];
    const int tid = threadIdx.x;
    const int bt = blockIdx.x;
    const int b = bt >> 6, t = bt & 63;
    const int warp = tid >> 5, lane = tid & 31;

    // ---------------- Phase 0: stage Z (stride 136) + small tensors ----------------
#pragma unroll
    for (int it = 0; it < 4; it++) {
        int idx = tid + it * TPB;              // idx = n*32 + dgroup
        int n = idx >> 5, dg = idx & 31;
        st4(sm + OZ + n*136 + dg*4, ld4(x + ((((size_t)b*32 + n)*64 + t)*128) + dg*4));
    }
    if (tid < 32) {
        sm[OSB + tid]      = b1g[tid];
        sm[OSB + 32 + tid] = W2g[tid];
        sm[OSB + 64 + tid] = pmask[b*32 + tid] ? 1.f : 0.f;
        if (tid == 0) { sm[OSB+96] = physw[0]; sm[OSB+97] = priorw[0]; sm[OSB+98] = b2g[0]; }
    }
    if (tid >= 64 && tid < 192) {              // W1e [j][e]
        int i = tid - 64;
        sm[OSB + 128 + i] = W1[(i>>2)*260 + 256 + (i&3)];
    }
    __syncthreads();

    // ---------------- Phase 0b: Z -> bf16 hi/lo (OSCR) ----------------
    cvt_split(sm + OZ, sm + OSCR, tid);
    __syncthreads();

    // ---------------- Phase 1: C1 = Z @ P -> OC (bf16 3-split mma) ----------------
    gemm_mma(sm + OSCR, g_Pbh, g_Pbl, sm + OC, nullptr, tid);
    __syncthreads();

    // ---------------- Phase 2a: build packed Z^T (ZTP u64[64][33]) in OSCR ----------------
#pragma unroll
    for (int it = 0; it < 4; it++) {
        int idx = tid + it * TPB;
        int n = idx >> 5, dg = idx & 31;
        float4 v = ld4(sm + OZ + n*136 + dg*4);
        stu(sm + OSCR + (dg*2 + 0)*66 + n*2, pk2(v.x, v.y));
        stu(sm + OSCR + (dg*2 + 1)*66 + n*2, pk2(v.z, v.w));
    }
    __syncthreads();

    // ---------------- Phase 2b: content = C1 @ Z^T -> LOG ----------------
    {
        u64 acc2[4] = {0ull, 0ull, 0ull, 0ull};
        for (int k = 0; k < 128; k += 4) {
            u64 zt01 = ldu(sm + OSCR + k*33      + lane*2);
            u64 zt23 = ldu(sm + OSCR + k*33 + 66 + lane*2);
#pragma unroll
            for (int i = 0; i < 4; i++) {
                ulonglong2 c2 = ldp2(sm + OC + (warp*4+i)*136 + k);
                acc2[i] = fma2(c2.x, zt01, acc2[i]);
                acc2[i] = fma2(c2.y, zt23, acc2[i]);
            }
        }
#pragma unroll
        for (int i = 0; i < 4; i++) {
            float2 f = upk2(acc2[i]);
            sm[OW + (warp*4+i)*36 + lane] = f.x + f.y;
        }
    }
    __syncthreads();   // ZTP reads done -> OSCR reusable for HQ/HKT

    // ---------------- Phase 4: H = Z @ gU (hq | hk) -- warp=4 rows, lane=j-pair ----------------
    {
        const int r0 = warp * 4;
        const int j2 = lane * 2;
        u64 acc4[4] = {0ull, 0ull, 0ull, 0ull};
#pragma unroll 4
        for (int k = 0; k < 128; k += 4) {
            u64 wr[4];
#pragma unroll
            for (int u = 0; u < 4; u++) wr[u] = ldu(&g_U[(k+u)*64 + j2]);
            float4 z[4];
#pragma unroll
            for (int i = 0; i < 4; i++) z[i] = ld4(sm + OZ + (r0 + i)*136 + k);
#pragma unroll
            for (int u = 0; u < 4; u++) {
#pragma unroll
                for (int i = 0; i < 4; i++) {
                    float a = (u==0) ? z[i].x : (u==1) ? z[i].y : (u==2) ? z[i].z : z[i].w;
                    acc4[i] = fma2(pk2(a, a), wr[u], acc4[i]);
                }
            }
        }
#pragma unroll
        for (int i = 0; i < 4; i++) {
            int n = r0 + i;
            if (j2 < 32) {                       // hq -> HQ[32][36] @ OSCR
                stu(sm + OSCR + n*36 + j2, acc4[i]);
            } else {                             // hk -> HKT[j][n] [32][33] @ OSCR+1152
                float2 f = upk2(acc4[i]);
                int j = j2 - 32;
                sm[OSCR + 1152 + (j+0)*33 + n] = f.x;
                sm[OSCR + 1152 + (j+1)*33 + n] = f.y;
            }
        }
    }

    // ---------------- Prefetch edge / prior ----------------
    const int pn = tid >> 3, pm0 = (tid & 7) << 2;
    float4 e4[4]; float lpr[4];
    {
        const float wf0 = __ldg(Wfuse+0), wf1 = __ldg(Wfuse+1), wf2 = __ldg(Wfuse+2),
                    wf3 = __ldg(Wfuse+3), wf4 = __ldg(Wfuse+4);
#pragma unroll
        for (int mm = 0; mm < 4; mm++) {
            size_t pair = (size_t)bt*1024 + pn*32 + pm0 + mm;
            e4[mm] = ld4(edge + pair*4);
            const float* ap = Aprior + pair*5;
            float p = ap[0]*wf0 + ap[1]*wf1 + ap[2]*wf2 + ap[3]*wf3 + ap[4]*wf4;
            if (!isfinite(p)) p = 0.f;
            p = fmaxf(p, 0.f);
            lpr[mm] = logf(p + 1e-6f);
        }
    }
    __syncthreads();

    // ---------------- Phase 5: phys MLP + prior + logits ----------------
    {
        float ph[4] = {0.f, 0.f, 0.f, 0.f};
#pragma unroll
        for (int j = 0; j < 32; j += 4) {
            float4 hqv = ld4(sm + OSCR + pn*36 + j);
            float4 b1v = ld4(sm + OSB + j);
            float4 w2v = ld4(sm + OSB + 32 + j);
            float hq4[4] = {hqv.x, hqv.y, hqv.z, hqv.w};
            float b14[4] = {b1v.x, b1v.y, b1v.z, b1v.w};
            float w24[4] = {w2v.x, w2v.y, w2v.z, w2v.w};
#pragma unroll
            for (int jj = 0; jj < 4; jj++) {
                int jc = j + jj;
                float hqb = hq4[jj] + b14[jj];
                float w2s = w24[jj];
                float4 we = ld4(sm + OSB + 128 + jc*4);
#pragma unroll
                for (int mm = 0; mm < 4; mm++) {
                    float h = hqb + sm[OSCR + 1152 + jc*33 + pm0 + mm]
                            + e4[mm].x*we.x + e4[mm].y*we.y
                            + e4[mm].z*we.z + e4[mm].w*we.w;
                    h = fmaxf(h, 0.f);
                    ph[mm] = fmaf(h, w2s, ph[mm]);
                }
            }
        }
        float pw = sm[OSB+96], prw = sm[OSB+97], b2v = sm[OSB+98];
        float mn = sm[OSB + 64 + pn];
#pragma unroll
        for (int mm = 0; mm < 4; mm++) {
            float lg = sm[OW + pn*36 + pm0 + mm]
                     + pw * (ph[mm] + b2v)
                     + prw * lpr[mm];
            if (mn != 0.f || sm[OSB + 64 + pm0 + mm] != 0.f) lg = -1e9f;
            sm[OW + pn*36 + pm0 + mm] = lg;
        }
    }
    __syncthreads();

    // ---------------- Phase 6: softmax (warp per 4 rows) ----------------
#pragma unroll
    for (int q = 0; q < 4; q++) {
        int n = warp*4 + q;
        float v = sm[OW + n*36 + lane];
        float mx = v;
#pragma unroll
        for (int off = 16; off > 0; off >>= 1)
            mx = fmaxf(mx, __shfl_xor_sync(0xffffffffu, mx, off));
        float e = expf(v - mx);
        float s = e;
#pragma unroll
        for (int off = 16; off > 0; off >>= 1)
            s += __shfl_xor_sync(0xffffffffu, s, off);
        sm[OW + n*36 + lane] = e / s;
    }
    __syncthreads();

    // ---------------- Phase 7: AZ = alpha @ Z -> OC ----------------
    {
        const int r0 = warp * 4;
        const int c0 = lane * 4;
        u64 acc[8];
#pragma unroll
        for (int i = 0; i < 8; i++) acc[i] = 0ull;
#pragma unroll 2
        for (int k = 0; k < 32; k += 4) {
            float4 a[4];
#pragma unroll
            for (int i = 0; i < 4; i++) a[i] = ld4(sm + OW + (r0 + i)*36 + k);
#pragma unroll
            for (int u = 0; u < 4; u++) {
                ulonglong2 zv = ldp2(sm + OZ + (k+u)*136 + c0);
#pragma unroll
                for (int i = 0; i < 4; i++) {
                    float av = (u==0) ? a[i].x : (u==1) ? a[i].y : (u==2) ? a[i].z : a[i].w;
                    u64 ad = pk2(av, av);
                    acc[i*2]   = fma2(ad, zv.x, acc[i*2]);
                    acc[i*2+1] = fma2(ad, zv.y, acc[i*2+1]);
                }
            }
        }
        __syncthreads();   // C1 in OC fully consumed (phase 2b)
#pragma unroll
        for (int i = 0; i < 4; i++)
            stp2(sm + OC + (r0+i)*136 + c0, acc[i*2], acc[i*2+1]);
    }
    __syncthreads();

    // ---------------- Phase 7b: AZ -> bf16 hi/lo (OSCR, over HQ/HKT) ----------------
    cvt_split(sm + OC, sm + OSCR, tid);
    __syncthreads();

    // ---------------- Phase 8: y = Z + AZ @ G -> OC (bf16 3-split mma) ----------------
    gemm_mma(sm + OSCR, g_Gbh, g_Gbl, sm + OC, sm + OZ, tid);
    __syncthreads();

    // ---------------- Phase 9: LayerNorm + masked store ----------------
    {
        float4 gv = __ldg(reinterpret_cast<const float4*>(gammag + lane*4));
        float4 bv = __ldg(reinterpret_cast<const float4*>(betag + lane*4));
#pragma unroll
        for (int q = 0; q < 4; q++) {
            int n = warp*4 + q;
            float4 y = ld4(sm + OC + n*136 + lane*4);
            float s  = y.x + y.y + y.z + y.w;
            float s2 = y.x*y.x + y.y*y.y + y.z*y.z + y.w*y.w;
#pragma unroll
            for (int off = 16; off > 0; off >>= 1) {
                s  += __shfl_xor_sync(0xffffffffu, s, off);
                s2 += __shfl_xor_sync(0xffffffffu, s2, off);
            }
            float mu   = s * (1.f/128.f);
            float var  = s2 * (1.f/128.f) - mu*mu;
            float rstd = rsqrtf(var + 1e-5f);
            float4 o;
            o.x = (y.x - mu)*rstd*gv.x + bv.x;
            o.y = (y.y - mu)*rstd*gv.y + bv.y;
            o.z = (y.z - mu)*rstd*gv.z + bv.z;
            o.w = (y.w - mu)*rstd*gv.w + bv.w;
            if (sm[OSB + 64 + n] != 0.f) o = make_float4(0.f, 0.f, 0.f, 0.f);
            reinterpret_cast<float4*>(out)[(((size_t)b*32 + n)*64 + t)*32 + lane] = o;
        }
    }
}

extern "C" void kernel_launch(void* const* d_in, const int* in_sizes, int n_in,
                              void* d_out, int out_size) {
    (void)in_sizes; (void)n_in; (void)out_size;
    const float* x      = (const float*)d_in[0];
    const float* edge   = (const float*)d_in[1];
    const float* Aprior = (const float*)d_in[2];
    const unsigned char* pmask = (const unsigned char*)d_in[3];
    const float* Wq     = (const float*)d_in[4];
    const float* Wk     = (const float*)d_in[5];
    const float* Wv     = (const float*)d_in[6];
    const float* Th     = (const float*)d_in[7];
    const float* Wfuse  = (const float*)d_in[8];
    const float* W1     = (const float*)d_in[9];
    const float* b1     = (const float*)d_in[10];
    const float* W2     = (const float*)d_in[11];
    const float* b2     = (const float*)d_in[12];
    const float* gamma  = (const float*)d_in[13];
    const float* beta   = (const float*)d_in[14];
    const float* physw  = (const float*)d_in[15];
    const float* priorw = (const float*)d_in[16];
    float* out = (float*)d_out;

    prep_kernel<<<192, 128>>>(Wq, Wk, Wv, Th, W1);

    cudaFuncSetAttribute(fused_gnn_kernel,
                         cudaFuncAttributeMaxDynamicSharedMemorySize, SMEMF * 4);
    fused_gnn_kernel<<<512, TPB, SMEMF * 4>>>(x, edge, Aprior, pmask, Wfuse, W1, b1, W2, b2,
                                              gamma, beta, physw, priorw, out);
}

// round 14
// speedup vs baseline: 1.4505x; 1.1091x over previous
#include <cuda_runtime.h>
#include <cuda_bf16.h>
#include <math.h>

#define TPB 256

typedef unsigned long long u64;
typedef unsigned int u32;

// bf16 hi/lo fragment-packed B operands (prep-computed):
// P,G: u32 index = ((ks*16 + nt)*32 + lane)*2 + breg ; u16 half = kin&1
__device__ u32 g_Pbh[8*16*32*2];
__device__ u32 g_Pbl[8*16*32*2];
__device__ u32 g_Gbh[8*16*32*2];
__device__ u32 g_Gbl[8*16*32*2];
// gU (128k x 64j): 8 ntiles
__device__ u32 g_Ubh[8*8*32*2];
__device__ u32 g_Ubl[8*8*32*2];

__device__ __forceinline__ float4 ld4(const float* p){ return *reinterpret_cast<const float4*>(p); }
__device__ __forceinline__ void st4(float* p, float4 v){ *reinterpret_cast<float4*>(p)=v; }
__device__ __forceinline__ u64 ldu(const float* p){ return *reinterpret_cast<const u64*>(p); }
__device__ __forceinline__ void stu(float* p, u64 v){ *reinterpret_cast<u64*>(p)=v; }
__device__ __forceinline__ ulonglong2 ldp2(const float* p){ return *reinterpret_cast<const ulonglong2*>(p); }
__device__ __forceinline__ void stp2(float* p, u64 a, u64 b){
    ulonglong2 v; v.x = a; v.y = b; *reinterpret_cast<ulonglong2*>(p) = v;
}
__device__ __forceinline__ u64 pk2(float x, float y){ u64 r; asm("mov.b64 %0,{%1,%2};":"=l"(r):"f"(x),"f"(y)); return r; }
__device__ __forceinline__ float2 upk2(u64 v){ float2 f; asm("mov.b64 {%0,%1},%2;":"=f"(f.x),"=f"(f.y):"l"(v)); return f; }
__device__ __forceinline__ u64 fma2(u64 a,u64 b,u64 c){ u64 d; asm("fma.rn.f32x2 %0,%1,%2,%3;":"=l"(d):"l"(a),"l"(b),"l"(c)); return d; }
__device__ __forceinline__ u64 add2(u64 a,u64 b){ u64 d; asm("add.rn.f32x2 %0,%1,%2;":"=l"(d):"l"(a),"l"(b)); return d; }

__device__ __forceinline__ void mma16816(float* c, const u32* a, u32 b0, u32 b1){
    asm("mma.sync.aligned.m16n8k16.row.col.f32.bf16.bf16.f32 "
        "{%0,%1,%2,%3},{%4,%5,%6,%7},{%8,%9},{%0,%1,%2,%3};"
        : "+f"(c[0]),"+f"(c[1]),"+f"(c[2]),"+f"(c[3])
        : "r"(a[0]),"r"(a[1]),"r"(a[2]),"r"(a[3]),"r"(b0),"r"(b1));
}
__device__ __forceinline__ void ldsm4(u32* r, u32 addr){
    asm volatile("ldmatrix.sync.aligned.m8n8.x4.shared.b16 {%0,%1,%2,%3},[%4];"
        : "=r"(r[0]),"=r"(r[1]),"=r"(r[2]),"=r"(r[3]) : "r"(addr));
}
__device__ __forceinline__ u32 bf2pk(float hi_src, float lo_src){
    u32 r; asm("cvt.rn.satfinite.bf16x2.f32 %0,%1,%2;" : "=r"(r) : "f"(hi_src), "f"(lo_src)); return r;
}

// ---------------- prep ----------------
// blocks 0..127: d = bx, k = tid: P[k][d], G[k][d] -> bf16 hi/lo frag arrays
// blocks 128..191: j = bx-128, k = tid: gU[k][j] -> bf16 hi/lo frag arrays
__global__ void prep_kernel(const float* __restrict__ Wq, const float* __restrict__ Wk,
                            const float* __restrict__ Wv, const float* __restrict__ Th,
                            const float* __restrict__ W1)
{
    const int bx = blockIdx.x, tid = threadIdx.x;
    const int k = tid;
    const int ks = k >> 4, kin = k & 15;
    const int breg = kin >> 3, rem = kin & 7, tq = rem >> 1, half = rem & 1;
    if (bx < 128) {
        const int d = bx;
        float accP = 0.f, accG = 0.f;
#pragma unroll 8
        for (int i = 0; i < 128; i++) {
            accP = fmaf(Wq[i*128 + k], Wk[i*128 + d], accP);
            accG = fmaf(Wv[i*128 + k], Th[d*128 + i], accG);
        }
        accP *= 0.08838834764831845f;
        const int nt = d >> 3, g = d & 7, ln = g*4 + tq;
        const int u16i = (((ks*16 + nt)*32 + ln)*2 + breg)*2 + half;

        unsigned short ph, pl, gh, gl;
        asm("cvt.rn.bf16.f32 %0,%1;" : "=h"(ph) : "f"(accP));
        float phf = __uint_as_float(((u32)ph) << 16);
        asm("cvt.rn.bf16.f32 %0,%1;" : "=h"(pl) : "f"(accP - phf));
        asm("cvt.rn.bf16.f32 %0,%1;" : "=h"(gh) : "f"(accG));
        float ghf = __uint_as_float(((u32)gh) << 16);
        asm("cvt.rn.bf16.f32 %0,%1;" : "=h"(gl) : "f"(accG - ghf));
        reinterpret_cast<unsigned short*>(g_Pbh)[u16i] = ph;
        reinterpret_cast<unsigned short*>(g_Pbl)[u16i] = pl;
        reinterpret_cast<unsigned short*>(g_Gbh)[u16i] = gh;
        reinterpret_cast<unsigned short*>(g_Gbl)[u16i] = gl;
    } else {
        const int j = bx - 128;
        const float* w1row = (j < 32) ? (W1 + j*260) : (W1 + (j-32)*260 + 128);
        const float* wc    = (j < 32) ? Wq : Wk;
        float acc = 0.f;
#pragma unroll 8
        for (int d = 0; d < 128; d++) acc = fmaf(w1row[d], wc[d*128 + k], acc);
        const int nt = j >> 3, g = j & 7, ln = g*4 + tq;
        const int u16i = (((ks*8 + nt)*32 + ln)*2 + breg)*2 + half;
        unsigned short uh, ul;
        asm("cvt.rn.bf16.f32 %0,%1;" : "=h"(uh) : "f"(acc));
        float uhf = __uint_as_float(((u32)uh) << 16);
        asm("cvt.rn.bf16.f32 %0,%1;" : "=h"(ul) : "f"(acc - uhf));
        reinterpret_cast<unsigned short*>(g_Ubh)[u16i] = uh;
        reinterpret_cast<unsigned short*>(g_Ubl)[u16i] = ul;
    }
}

// -------- shared memory layout (float offsets) --------
#define OZ    0         // Z [32][136] = 4352 (persistent)
#define OC    4352      // C1 -> AZ -> y [32][136] = 4352
#define OSCR  8704      // 4224: Zbf/AZbf hi[2048]+lo[2048] | ZTP u64[64][33]=4224 | HQ[32][36]@+0, HKT[32][33]@+1152
#define OSB   12928     // b1@0, W2@32, mask@64, consts@96, W1e@128 (256)
#define OW    13184     // LOG [32][36] = 1152
#define SMEMF 14336     // 57344 bytes -> 4 CTAs/SM

// Convert src[32][136] fp32 -> bf16 hi/lo tiles at sDst (hi @+0, lo @+2048 floats),
// row n = 64 floats (128 bf16), 16B blocks XOR-swizzled by (n&7).
__device__ __forceinline__ void cvt_split(const float* __restrict__ src, float* sDst, int tid){
    const int n = tid >> 3, cblk = tid & 7;
    const float* sp = src + n*136 + cblk*16;
    u32 hi[8], lo[8];
#pragma unroll
    for (int i = 0; i < 4; i++){
        float4 v = ld4(sp + i*4);
        u32 h0 = bf2pk(v.y, v.x);
        float hx = __uint_as_float(h0 << 16), hy = __uint_as_float(h0 & 0xffff0000u);
        u32 l0 = bf2pk(v.y - hy, v.x - hx);
        u32 h1 = bf2pk(v.w, v.z);
        float hz = __uint_as_float(h1 << 16), hw = __uint_as_float(h1 & 0xffff0000u);
        u32 l1 = bf2pk(v.w - hw, v.z - hz);
        hi[i*2] = h0; hi[i*2+1] = h1; lo[i*2] = l0; lo[i*2+1] = l1;
    }
    const int b0 = (cblk*2) ^ (n & 7), b1 = (cblk*2 + 1) ^ (n & 7);
    st4(sDst + n*64 + b0*4, make_float4(__uint_as_float(hi[0]), __uint_as_float(hi[1]),
                                        __uint_as_float(hi[2]), __uint_as_float(hi[3])));
    st4(sDst + n*64 + b1*4, make_float4(__uint_as_float(hi[4]), __uint_as_float(hi[5]),
                                        __uint_as_float(hi[6]), __uint_as_float(hi[7])));
    st4(sDst + 2048 + n*64 + b0*4, make_float4(__uint_as_float(lo[0]), __uint_as_float(lo[1]),
                                               __uint_as_float(lo[2]), __uint_as_float(lo[3])));
    st4(sDst + 2048 + n*64 + b1*4, make_float4(__uint_as_float(lo[4]), __uint_as_float(lo[5]),
                                               __uint_as_float(lo[6]), __uint_as_float(lo[7])));
}

// D[32][136] = A(bf16 split tiles in smem) @ B(frag-packed global) (+resid[32][136])
__device__ __forceinline__ void gemm_mma(const float* __restrict__ sAbf,
                                         const u32* __restrict__ Bh, const u32* __restrict__ Bl,
                                         float* dst, const float* resid, int tid)
{
    const int warp = tid >> 5, lane = tid & 31;
    const int mw = warp & 1, ntg = warp >> 1;
    const int m = mw*16 + (lane & 7) + ((lane >> 3) & 1)*8;
    const int kbh = lane >> 4;
    const u32 base = (u32)__cvta_generic_to_shared(sAbf);

    float c[4][4];
#pragma unroll
    for (int nt = 0; nt < 4; nt++){ c[nt][0]=0.f; c[nt][1]=0.f; c[nt][2]=0.f; c[nt][3]=0.f; }

#pragma unroll
    for (int ks = 0; ks < 8; ks++){
        const int kb = ks*2 + kbh;
        const u32 off = (u32)(m*256 + ((kb ^ (m & 7)) << 4));
        u32 ah[4], al[4];
        ldsm4(ah, base + off);
        ldsm4(al, base + 8192 + off);
        const u32* bhp = Bh + ((ks*16 + ntg*4)*32 + lane)*2;
        const u32* blp = Bl + ((ks*16 + ntg*4)*32 + lane)*2;
#pragma unroll
        for (int nt = 0; nt < 4; nt++){
            uint2 bh = *reinterpret_cast<const uint2*>(bhp + nt*64);
            uint2 bl = *reinterpret_cast<const uint2*>(blp + nt*64);
            mma16816(c[nt], ah, bh.x, bh.y);
            mma16816(c[nt], ah, bl.x, bl.y);
            mma16816(c[nt], al, bh.x, bh.y);
        }
    }
    const int r0 = mw*16 + (lane >> 2), r1 = r0 + 8;
    const int cb = ntg*32 + (lane & 3)*2;
#pragma unroll
    for (int nt = 0; nt < 4; nt++){
        const int col = cb + nt*8;
        float2 v0 = make_float2(c[nt][0], c[nt][1]);
        float2 v1 = make_float2(c[nt][2], c[nt][3]);
        if (resid){
            float2 z0 = *reinterpret_cast<const float2*>(resid + r0*136 + col);
            float2 z1 = *reinterpret_cast<const float2*>(resid + r1*136 + col);
            v0.x += z0.x; v0.y += z0.y; v1.x += z1.x; v1.y += z1.y;
        }
        *reinterpret_cast<float2*>(dst + r0*136 + col) = v0;
        *reinterpret_cast<float2*>(dst + r1*136 + col) = v1;
    }
}

__global__ __launch_bounds__(TPB, 4)
void fused_gnn_kernel(const float* __restrict__ x, const float* __restrict__ edge,
                      const float* __restrict__ Aprior, const unsigned char* __restrict__ pmask,
                      const float* __restrict__ Wfuse, const float* __restrict__ W1,
                      const float* __restrict__ b1g, const float* __restrict__ W2g,
                      const float* __restrict__ b2g, const float* __restrict__ gammag,
                      const float* __restrict__ betag, const float* __restrict__ physw,
                      const float* __restrict__ priorw, float* __restrict__ out)
{
    extern __shared__ float sm[];
    const int tid = threadIdx.x;
    const int bt = blockIdx.x;
    const int b = bt >> 6, t = bt & 63;
    const int warp = tid >> 5, lane = tid & 31;

    // ---------------- Phase 0: stage Z (stride 136) + small tensors ----------------
#pragma unroll
    for (int it = 0; it < 4; it++) {
        int idx = tid + it * TPB;              // idx = n*32 + dgroup
        int n = idx >> 5, dg = idx & 31;
        st4(sm + OZ + n*136 + dg*4, ld4(x + ((((size_t)b*32 + n)*64 + t)*128) + dg*4));
    }
    if (tid < 32) {
        sm[OSB + tid]      = b1g[tid];
        sm[OSB + 32 + tid] = W2g[tid];
        sm[OSB + 64 + tid] = pmask[b*32 + tid] ? 1.f : 0.f;
        if (tid == 0) { sm[OSB+96] = physw[0]; sm[OSB+97] = priorw[0]; sm[OSB+98] = b2g[0]; }
    }
    if (tid >= 64 && tid < 192) {              // W1e [j][e]
        int i = tid - 64;
        sm[OSB + 128 + i] = W1[(i>>2)*260 + 256 + (i&3)];
    }
    __syncthreads();

    // ---------------- Phase 0b: Z -> bf16 hi/lo (OSCR) ----------------
    cvt_split(sm + OZ, sm + OSCR, tid);
    __syncthreads();

    // ---------------- Phase 1: C1 = Z @ P -> OC (bf16 3-split mma) ----------------
    gemm_mma(sm + OSCR, g_Pbh, g_Pbl, sm + OC, nullptr, tid);

    // ---------------- Phase 4-mma: H = Z @ gU (A = Zbf, held in regs) ----------------
    float hc[2][4];
    {
        const int mw = warp & 1, ntg = warp >> 1;
        const int m = mw*16 + (lane & 7) + ((lane >> 3) & 1)*8;
        const int kbh = lane >> 4;
        const u32 base = (u32)__cvta_generic_to_shared(sm + OSCR);
#pragma unroll
        for (int nt = 0; nt < 2; nt++){ hc[nt][0]=0.f; hc[nt][1]=0.f; hc[nt][2]=0.f; hc[nt][3]=0.f; }
#pragma unroll
        for (int ks = 0; ks < 8; ks++){
            const int kb = ks*2 + kbh;
            const u32 off = (u32)(m*256 + ((kb ^ (m & 7)) << 4));
            u32 ah[4], al[4];
            ldsm4(ah, base + off);
            ldsm4(al, base + 8192 + off);
            const u32* bhp = g_Ubh + ((ks*8 + ntg*2)*32 + lane)*2;
            const u32* blp = g_Ubl + ((ks*8 + ntg*2)*32 + lane)*2;
#pragma unroll
            for (int nt = 0; nt < 2; nt++){
                uint2 bh = *reinterpret_cast<const uint2*>(bhp + nt*64);
                uint2 bl = *reinterpret_cast<const uint2*>(blp + nt*64);
                mma16816(hc[nt], ah, bh.x, bh.y);
                mma16816(hc[nt], ah, bl.x, bl.y);
                mma16816(hc[nt], al, bh.x, bh.y);
            }
        }
    }
    __syncthreads();   // Zbf reads done; C1 visible

    // ---------------- Phase 2a: build packed Z^T (ZTP u64[64][33]) over Zbf ----------------
#pragma unroll
    for (int it = 0; it < 4; it++) {
        int idx = tid + it * TPB;
        int n = idx >> 5, dg = idx & 31;
        float4 v = ld4(sm + OZ + n*136 + dg*4);
        stu(sm + OSCR + (dg*2 + 0)*66 + n*2, pk2(v.x, v.y));
        stu(sm + OSCR + (dg*2 + 1)*66 + n*2, pk2(v.z, v.w));
    }
    __syncthreads();

    // ---------------- Phase 2b: content = C1 @ Z^T -> LOG ----------------
    {
        u64 acc2[4] = {0ull, 0ull, 0ull, 0ull};
        for (int k = 0; k < 128; k += 4) {
            u64 zt01 = ldu(sm + OSCR + k*33      + lane*2);
            u64 zt23 = ldu(sm + OSCR + k*33 + 66 + lane*2);
#pragma unroll
            for (int i = 0; i < 4; i++) {
                ulonglong2 c2 = ldp2(sm + OC + (warp*4+i)*136 + k);
                acc2[i] = fma2(c2.x, zt01, acc2[i]);
                acc2[i] = fma2(c2.y, zt23, acc2[i]);
            }
        }
#pragma unroll
        for (int i = 0; i < 4; i++) {
            float2 f = upk2(acc2[i]);
            sm[OW + (warp*4+i)*36 + lane] = f.x + f.y;
        }
    }
    __syncthreads();   // ZTP dead -> OSCR reusable for HQ/HKT

    // ---------------- Phase 4-store: H frags -> HQ[32][36]@OSCR, HKT[32][33]@OSCR+1152 ----------------
    {
        const int mw = warp & 1, ntg = warp >> 1;
#pragma unroll
        for (int nt = 0; nt < 2; nt++) {
#pragma unroll
            for (int i = 0; i < 4; i++) {
                int row = mw*16 + (lane >> 2) + ((i >> 1) & 1)*8;
                int j   = ntg*16 + nt*8 + (lane & 3)*2 + (i & 1);
                float v = hc[nt][i];
                if (j < 32) sm[OSCR + row*36 + j] = v;
                else        sm[OSCR + 1152 + (j-32)*33 + row] = v;
            }
        }
    }

    // ---------------- Prefetch edge / prior ----------------
    const int pn = tid >> 3, pm0 = (tid & 7) << 2;
    float4 e4[4]; float lpr[4];
    {
        const float wf0 = __ldg(Wfuse+0), wf1 = __ldg(Wfuse+1), wf2 = __ldg(Wfuse+2),
                    wf3 = __ldg(Wfuse+3), wf4 = __ldg(Wfuse+4);
#pragma unroll
        for (int mm = 0; mm < 4; mm++) {
            size_t pair = (size_t)bt*1024 + pn*32 + pm0 + mm;
            e4[mm] = ld4(edge + pair*4);
            const float* ap = Aprior + pair*5;
            float p = ap[0]*wf0 + ap[1]*wf1 + ap[2]*wf2 + ap[3]*wf3 + ap[4]*wf4;
            if (!isfinite(p)) p = 0.f;
            p = fmaxf(p, 0.f);
            lpr[mm] = logf(p + 1e-6f);
        }
    }
    __syncthreads();

    // ---------------- Phase 5: phys MLP + prior + logits ----------------
    {
        float ph[4] = {0.f, 0.f, 0.f, 0.f};
#pragma unroll
        for (int j = 0; j < 32; j += 4) {
            float4 hqv = ld4(sm + OSCR + pn*36 + j);
            float4 b1v = ld4(sm + OSB + j);
            float4 w2v = ld4(sm + OSB + 32 + j);
            float hq4[4] = {hqv.x, hqv.y, hqv.z, hqv.w};
            float b14[4] = {b1v.x, b1v.y, b1v.z, b1v.w};
            float w24[4] = {w2v.x, w2v.y, w2v.z, w2v.w};
#pragma unroll
            for (int jj = 0; jj < 4; jj++) {
                int jc = j + jj;
                float hqb = hq4[jj] + b14[jj];
                float w2s = w24[jj];
                float4 we = ld4(sm + OSB + 128 + jc*4);
#pragma unroll
                for (int mm = 0; mm < 4; mm++) {
                    float h = hqb + sm[OSCR + 1152 + jc*33 + pm0 + mm]
                            + e4[mm].x*we.x + e4[mm].y*we.y
                            + e4[mm].z*we.z + e4[mm].w*we.w;
                    h = fmaxf(h, 0.f);
                    ph[mm] = fmaf(h, w2s, ph[mm]);
                }
            }
        }
        float pw = sm[OSB+96], prw = sm[OSB+97], b2v = sm[OSB+98];
        float mn = sm[OSB + 64 + pn];
#pragma unroll
        for (int mm = 0; mm < 4; mm++) {
            float lg = sm[OW + pn*36 + pm0 + mm]
                     + pw * (ph[mm] + b2v)
                     + prw * lpr[mm];
            if (mn != 0.f || sm[OSB + 64 + pm0 + mm] != 0.f) lg = -1e9f;
            sm[OW + pn*36 + pm0 + mm] = lg;
        }
    }
    __syncthreads();

    // ---------------- Phase 6: softmax (warp per 4 rows) ----------------
#pragma unroll
    for (int q = 0; q < 4; q++) {
        int n = warp*4 + q;
        float v = sm[OW + n*36 + lane];
        float mx = v;
#pragma unroll
        for (int off = 16; off > 0; off >>= 1)
            mx = fmaxf(mx, __shfl_xor_sync(0xffffffffu, mx, off));
        float e = expf(v - mx);
        float s = e;
#pragma unroll
        for (int off = 16; off > 0; off >>= 1)
            s += __shfl_xor_sync(0xffffffffu, s, off);
        sm[OW + n*36 + lane] = e / s;
    }
    __syncthreads();

    // ---------------- Phase 7: AZ = alpha @ Z -> OC ----------------
    {
        const int r0 = warp * 4;
        const int c0 = lane * 4;
        u64 acc[8];
#pragma unroll
        for (int i = 0; i < 8; i++) acc[i] = 0ull;
#pragma unroll 2
        for (int k = 0; k < 32; k += 4) {
            float4 a[4];
#pragma unroll
            for (int i = 0; i < 4; i++) a[i] = ld4(sm + OW + (r0 + i)*36 + k);
#pragma unroll
            for (int u = 0; u < 4; u++) {
                ulonglong2 zv = ldp2(sm + OZ + (k+u)*136 + c0);
#pragma unroll
                for (int i = 0; i < 4; i++) {
                    float av = (u==0) ? a[i].x : (u==1) ? a[i].y : (u==2) ? a[i].z : a[i].w;
                    u64 ad = pk2(av, av);
                    acc[i*2]   = fma2(ad, zv.x, acc[i*2]);
                    acc[i*2+1] = fma2(ad, zv.y, acc[i*2+1]);
                }
            }
        }
        __syncthreads();   // C1 in OC fully consumed (phase 2b)
#pragma unroll
        for (int i = 0; i < 4; i++)
            stp2(sm + OC + (r0+i)*136 + c0, acc[i*2], acc[i*2+1]);
    }
    __syncthreads();

    // ---------------- Phase 7b: AZ -> bf16 hi/lo (OSCR, over HQ/HKT) ----------------
    cvt_split(sm + OC, sm + OSCR, tid);
    __syncthreads();

    // ---------------- Phase 8: y = Z + AZ @ G -> OC (bf16 3-split mma) ----------------
    gemm_mma(sm + OSCR, g_Gbh, g_Gbl, sm + OC, sm + OZ, tid);
    __syncthreads();

    // ---------------- Phase 9: LayerNorm + masked store ----------------
    {
        float4 gv = __ldg(reinterpret_cast<const float4*>(gammag + lane*4));
        float4 bv = __ldg(reinterpret_cast<const float4*>(betag + lane*4));
#pragma unroll
        for (int q = 0; q < 4; q++) {
            int n = warp*4 + q;
            float4 y = ld4(sm + OC + n*136 + lane*4);
            float s  = y.x + y.y + y.z + y.w;
            float s2 = y.x*y.x + y.y*y.y + y.z*y.z + y.w*y.w;
#pragma unroll
            for (int off = 16; off > 0; off >>= 1) {
                s  += __shfl_xor_sync(0xffffffffu, s, off);
                s2 += __shfl_xor_sync(0xffffffffu, s2, off);
            }
            float mu   = s * (1.f/128.f);
            float var  = s2 * (1.f/128.f) - mu*mu;
            float rstd = rsqrtf(var + 1e-5f);
            float4 o;
            o.x = (y.x - mu)*rstd*gv.x + bv.x;
            o.y = (y.y - mu)*rstd*gv.y + bv.y;
            o.z = (y.z - mu)*rstd*gv.z + bv.z;
            o.w = (y.w - mu)*rstd*gv.w + bv.w;
            if (sm[OSB + 64 + n] != 0.f) o = make_float4(0.f, 0.f, 0.f, 0.f);
            reinterpret_cast<float4*>(out)[(((size_t)b*32 + n)*64 + t)*32 + lane] = o;
        }
    }
}

extern "C" void kernel_launch(void* const* d_in, const int* in_sizes, int n_in,
                              void* d_out, int out_size) {
    (void)in_sizes; (void)n_in; (void)out_size;
    const float* x      = (const float*)d_in[0];
    const float* edge   = (const float*)d_in[1];
    const float* Aprior = (const float*)d_in[2];
    const unsigned char* pmask = (const unsigned char*)d_in[3];
    const float* Wq     = (const float*)d_in[4];
    const float* Wk     = (const float*)d_in[5];
    const float* Wv     = (const float*)d_in[6];
    const float* Th     = (const float*)d_in[7];
    const float* Wfuse  = (const float*)d_in[8];
    const float* W1     = (const float*)d_in[9];
    const float* b1     = (const float*)d_in[10];
    const float* W2     = (const float*)d_in[11];
    const float* b2     = (const float*)d_in[12];
    const float* gamma  = (const float*)d_in[13];
    const float* beta   = (const float*)d_in[14];
    const float* physw  = (const float*)d_in[15];
    const float* priorw = (const float*)d_in[16];
    float* out = (float*)d_out;

    prep_kernel<<<192, 128>>>(Wq, Wk, Wv, Th, W1);

    cudaFuncSetAttribute(fused_gnn_kernel,
                         cudaFuncAttributeMaxDynamicSharedMemorySize, SMEMF * 4);
    fused_gnn_kernel<<<512, TPB, SMEMF * 4>>>(x, edge, Aprior, pmask, Wfuse, W1, b1, W2, b2,
                                              gamma, beta, physw, priorw, out);
}

// round 15
// speedup vs baseline: 1.5777x; 1.0877x over previous
#include <cuda_runtime.h>
#include <cuda_bf16.h>
#include <math.h>

#define TPB 256

typedef unsigned long long u64;
typedef unsigned int u32;

// bf16 hi/lo fragment-packed B operands (prep-computed):
__device__ u32 g_Pbh[8*16*32*2];
__device__ u32 g_Pbl[8*16*32*2];
__device__ u32 g_Gbh[8*16*32*2];
__device__ u32 g_Gbl[8*16*32*2];
__device__ u32 g_Ubh[8*8*32*2];
__device__ u32 g_Ubl[8*8*32*2];

__device__ __forceinline__ float4 ld4(const float* p){ return *reinterpret_cast<const float4*>(p); }
__device__ __forceinline__ void st4(float* p, float4 v){ *reinterpret_cast<float4*>(p)=v; }
__device__ __forceinline__ u64 ldu(const float* p){ return *reinterpret_cast<const u64*>(p); }
__device__ __forceinline__ void stu(float* p, u64 v){ *reinterpret_cast<u64*>(p)=v; }
__device__ __forceinline__ ulonglong2 ldp2(const float* p){ return *reinterpret_cast<const ulonglong2*>(p); }
__device__ __forceinline__ void stp2(float* p, u64 a, u64 b){
    ulonglong2 v; v.x = a; v.y = b; *reinterpret_cast<ulonglong2*>(p) = v;
}
__device__ __forceinline__ u64 pk2(float x, float y){ u64 r; asm("mov.b64 %0,{%1,%2};":"=l"(r):"f"(x),"f"(y)); return r; }
__device__ __forceinline__ float2 upk2(u64 v){ float2 f; asm("mov.b64 {%0,%1},%2;":"=f"(f.x),"=f"(f.y):"l"(v)); return f; }
__device__ __forceinline__ u64 fma2(u64 a,u64 b,u64 c){ u64 d; asm("fma.rn.f32x2 %0,%1,%2,%3;":"=l"(d):"l"(a),"l"(b),"l"(c)); return d; }
__device__ __forceinline__ u64 add2(u64 a,u64 b){ u64 d; asm("add.rn.f32x2 %0,%1,%2;":"=l"(d):"l"(a),"l"(b)); return d; }

__device__ __forceinline__ void mma16816(float* c, const u32* a, u32 b0, u32 b1){
    asm("mma.sync.aligned.m16n8k16.row.col.f32.bf16.bf16.f32 "
        "{%0,%1,%2,%3},{%4,%5,%6,%7},{%8,%9},{%0,%1,%2,%3};"
        : "+f"(c[0]),"+f"(c[1]),"+f"(c[2]),"+f"(c[3])
        : "r"(a[0]),"r"(a[1]),"r"(a[2]),"r"(a[3]),"r"(b0),"r"(b1));
}
__device__ __forceinline__ void ldsm4(u32* r, u32 addr){
    asm volatile("ldmatrix.sync.aligned.m8n8.x4.shared.b16 {%0,%1,%2,%3},[%4];"
        : "=r"(r[0]),"=r"(r[1]),"=r"(r[2]),"=r"(r[3]) : "r"(addr));
}
__device__ __forceinline__ void ldsm2(u32* r, u32 addr){
    asm volatile("ldmatrix.sync.aligned.m8n8.x2.shared.b16 {%0,%1},[%2];"
        : "=r"(r[0]),"=r"(r[1]) : "r"(addr));
}
__device__ __forceinline__ u32 bf2pk(float hi_src, float lo_src){
    u32 r; asm("cvt.rn.satfinite.bf16x2.f32 %0,%1,%2;" : "=r"(r) : "f"(hi_src), "f"(lo_src)); return r;
}

// ---------------- prep (unchanged from round 14) ----------------
__global__ void prep_kernel(const float* __restrict__ Wq, const float* __restrict__ Wk,
                            const float* __restrict__ Wv, const float* __restrict__ Th,
                            const float* __restrict__ W1)
{
    const int bx = blockIdx.x, tid = threadIdx.x;
    const int k = tid;
    const int ks = k >> 4, kin = k & 15;
    const int breg = kin >> 3, rem = kin & 7, tq = rem >> 1, half = rem & 1;
    if (bx < 128) {
        const int d = bx;
        float accP = 0.f, accG = 0.f;
#pragma unroll 8
        for (int i = 0; i < 128; i++) {
            accP = fmaf(Wq[i*128 + k], Wk[i*128 + d], accP);
            accG = fmaf(Wv[i*128 + k], Th[d*128 + i], accG);
        }
        accP *= 0.08838834764831845f;
        const int nt = d >> 3, g = d & 7, ln = g*4 + tq;
        const int u16i = (((ks*16 + nt)*32 + ln)*2 + breg)*2 + half;
        unsigned short ph, pl, gh, gl;
        asm("cvt.rn.bf16.f32 %0,%1;" : "=h"(ph) : "f"(accP));
        float phf = __uint_as_float(((u32)ph) << 16);
        asm("cvt.rn.bf16.f32 %0,%1;" : "=h"(pl) : "f"(accP - phf));
        asm("cvt.rn.bf16.f32 %0,%1;" : "=h"(gh) : "f"(accG));
        float ghf = __uint_as_float(((u32)gh) << 16);
        asm("cvt.rn.bf16.f32 %0,%1;" : "=h"(gl) : "f"(accG - ghf));
        reinterpret_cast<unsigned short*>(g_Pbh)[u16i] = ph;
        reinterpret_cast<unsigned short*>(g_Pbl)[u16i] = pl;
        reinterpret_cast<unsigned short*>(g_Gbh)[u16i] = gh;
        reinterpret_cast<unsigned short*>(g_Gbl)[u16i] = gl;
    } else {
        const int j = bx - 128;
        const float* w1row = (j < 32) ? (W1 + j*260) : (W1 + (j-32)*260 + 128);
        const float* wc    = (j < 32) ? Wq : Wk;
        float acc = 0.f;
#pragma unroll 8
        for (int d = 0; d < 128; d++) acc = fmaf(w1row[d], wc[d*128 + k], acc);
        const int nt = j >> 3, g = j & 7, ln = g*4 + tq;
        const int u16i = (((ks*8 + nt)*32 + ln)*2 + breg)*2 + half;
        unsigned short uh, ul;
        asm("cvt.rn.bf16.f32 %0,%1;" : "=h"(uh) : "f"(acc));
        float uhf = __uint_as_float(((u32)uh) << 16);
        asm("cvt.rn.bf16.f32 %0,%1;" : "=h"(ul) : "f"(acc - uhf));
        reinterpret_cast<unsigned short*>(g_Ubh)[u16i] = uh;
        reinterpret_cast<unsigned short*>(g_Ubl)[u16i] = ul;
    }
}

// -------- shared memory layout (float offsets) --------
#define OZ    0         // Z [32][136] = 4352 (persistent)
#define OC    4352      // C1 fp32 -> C1bf -> HQ[32][36]@+0,HKT[32][33]@+1152 -> AZ -> y  (4352)
#define OSCR  8704      // Zbf hi[2048]+lo[2048] (ph0b..content) -> AZbf (ph7b..8)  (4224)
#define OSB   12928     // b1@0, W2@32, mask@64, consts@96, W1e@128 (256)
#define OW    13184     // LOG [32][36] = 1152
#define SMEMF 14336     // 57344 bytes -> 4 CTAs/SM

// src[32][136] fp32 -> bf16 hi/lo tiles (hi @+0, lo @+2048), swizzled 16B blocks.
__device__ __forceinline__ void cvt_split(const float* __restrict__ src, float* sDst, int tid){
    const int n = tid >> 3, cblk = tid & 7;
    const float* sp = src + n*136 + cblk*16;
    u32 hi[8], lo[8];
#pragma unroll
    for (int i = 0; i < 4; i++){
        float4 v = ld4(sp + i*4);
        u32 h0 = bf2pk(v.y, v.x);
        float hx = __uint_as_float(h0 << 16), hy = __uint_as_float(h0 & 0xffff0000u);
        u32 l0 = bf2pk(v.y - hy, v.x - hx);
        u32 h1 = bf2pk(v.w, v.z);
        float hz = __uint_as_float(h1 << 16), hw = __uint_as_float(h1 & 0xffff0000u);
        u32 l1 = bf2pk(v.w - hw, v.z - hz);
        hi[i*2] = h0; hi[i*2+1] = h1; lo[i*2] = l0; lo[i*2+1] = l1;
    }
    const int b0 = (cblk*2) ^ (n & 7), b1 = (cblk*2 + 1) ^ (n & 7);
    st4(sDst + n*64 + b0*4, make_float4(__uint_as_float(hi[0]), __uint_as_float(hi[1]),
                                        __uint_as_float(hi[2]), __uint_as_float(hi[3])));
    st4(sDst + n*64 + b1*4, make_float4(__uint_as_float(hi[4]), __uint_as_float(hi[5]),
                                        __uint_as_float(hi[6]), __uint_as_float(hi[7])));
    st4(sDst + 2048 + n*64 + b0*4, make_float4(__uint_as_float(lo[0]), __uint_as_float(lo[1]),
                                               __uint_as_float(lo[2]), __uint_as_float(lo[3])));
    st4(sDst + 2048 + n*64 + b1*4, make_float4(__uint_as_float(lo[4]), __uint_as_float(lo[5]),
                                               __uint_as_float(lo[6]), __uint_as_float(lo[7])));
}

// In-place variant: read fp32 [32][136] from region, barrier, write bf tiles over it.
__device__ __forceinline__ void cvt_split_inplace(float* region, int tid){
    const int n = tid >> 3, cblk = tid & 7;
    const float* sp = region + n*136 + cblk*16;
    u32 hi[8], lo[8];
#pragma unroll
    for (int i = 0; i < 4; i++){
        float4 v = ld4(sp + i*4);
        u32 h0 = bf2pk(v.y, v.x);
        float hx = __uint_as_float(h0 << 16), hy = __uint_as_float(h0 & 0xffff0000u);
        u32 l0 = bf2pk(v.y - hy, v.x - hx);
        u32 h1 = bf2pk(v.w, v.z);
        float hz = __uint_as_float(h1 << 16), hw = __uint_as_float(h1 & 0xffff0000u);
        u32 l1 = bf2pk(v.w - hw, v.z - hz);
        hi[i*2] = h0; hi[i*2+1] = h1; lo[i*2] = l0; lo[i*2+1] = l1;
    }
    __syncthreads();   // all reads done before overwriting
    const int b0 = (cblk*2) ^ (n & 7), b1 = (cblk*2 + 1) ^ (n & 7);
    st4(region + n*64 + b0*4, make_float4(__uint_as_float(hi[0]), __uint_as_float(hi[1]),
                                          __uint_as_float(hi[2]), __uint_as_float(hi[3])));
    st4(region + n*64 + b1*4, make_float4(__uint_as_float(hi[4]), __uint_as_float(hi[5]),
                                          __uint_as_float(hi[6]), __uint_as_float(hi[7])));
    st4(region + 2048 + n*64 + b0*4, make_float4(__uint_as_float(lo[0]), __uint_as_float(lo[1]),
                                                 __uint_as_float(lo[2]), __uint_as_float(lo[3])));
    st4(region + 2048 + n*64 + b1*4, make_float4(__uint_as_float(lo[4]), __uint_as_float(lo[5]),
                                                 __uint_as_float(lo[6]), __uint_as_float(lo[7])));
}

// D[32][136] = A(bf16 split tiles) @ B(frag-packed global) (+resid)
__device__ __forceinline__ void gemm_mma(const float* __restrict__ sAbf,
                                         const u32* __restrict__ Bh, const u32* __restrict__ Bl,
                                         float* dst, const float* resid, int tid)
{
    const int warp = tid >> 5, lane = tid & 31;
    const int mw = warp & 1, ntg = warp >> 1;
    const int m = mw*16 + (lane & 7) + ((lane >> 3) & 1)*8;
    const int kbh = lane >> 4;
    const u32 base = (u32)__cvta_generic_to_shared(sAbf);

    float c[4][4];
#pragma unroll
    for (int nt = 0; nt < 4; nt++){ c[nt][0]=0.f; c[nt][1]=0.f; c[nt][2]=0.f; c[nt][3]=0.f; }
#pragma unroll
    for (int ks = 0; ks < 8; ks++){
        const int kb = ks*2 + kbh;
        const u32 off = (u32)(m*256 + ((kb ^ (m & 7)) << 4));
        u32 ah[4], al[4];
        ldsm4(ah, base + off);
        ldsm4(al, base + 8192 + off);
        const u32* bhp = Bh + ((ks*16 + ntg*4)*32 + lane)*2;
        const u32* blp = Bl + ((ks*16 + ntg*4)*32 + lane)*2;
#pragma unroll
        for (int nt = 0; nt < 4; nt++){
            uint2 bh = *reinterpret_cast<const uint2*>(bhp + nt*64);
            uint2 bl = *reinterpret_cast<const uint2*>(blp + nt*64);
            mma16816(c[nt], ah, bh.x, bh.y);
            mma16816(c[nt], ah, bl.x, bl.y);
            mma16816(c[nt], al, bh.x, bh.y);
        }
    }
    const int r0 = mw*16 + (lane >> 2), r1 = r0 + 8;
    const int cb = ntg*32 + (lane & 3)*2;
#pragma unroll
    for (int nt = 0; nt < 4; nt++){
        const int col = cb + nt*8;
        float2 v0 = make_float2(c[nt][0], c[nt][1]);
        float2 v1 = make_float2(c[nt][2], c[nt][3]);
        if (resid){
            float2 z0 = *reinterpret_cast<const float2*>(resid + r0*136 + col);
            float2 z1 = *reinterpret_cast<const float2*>(resid + r1*136 + col);
            v0.x += z0.x; v0.y += z0.y; v1.x += z1.x; v1.y += z1.y;
        }
        *reinterpret_cast<float2*>(dst + r0*136 + col) = v0;
        *reinterpret_cast<float2*>(dst + r1*136 + col) = v1;
    }
}

__global__ __launch_bounds__(TPB, 4)
void fused_gnn_kernel(const float* __restrict__ x, const float* __restrict__ edge,
                      const float* __restrict__ Aprior, const unsigned char* __restrict__ pmask,
                      const float* __restrict__ Wfuse, const float* __restrict__ W1,
                      const float* __restrict__ b1g, const float* __restrict__ W2g,
                      const float* __restrict__ b2g, const float* __restrict__ gammag,
                      const float* __restrict__ betag, const float* __restrict__ physw,
                      const float* __restrict__ priorw, float* __restrict__ out)
{
    extern __shared__ float sm[];
    const int tid = threadIdx.x;
    const int bt = blockIdx.x;
    const int b = bt >> 6, t = bt & 63;
    const int warp = tid >> 5, lane = tid & 31;

    // ---------------- Phase 0: stage Z + small tensors ----------------
#pragma unroll
    for (int it = 0; it < 4; it++) {
        int idx = tid + it * TPB;
        int n = idx >> 5, dg = idx & 31;
        st4(sm + OZ + n*136 + dg*4, ld4(x + ((((size_t)b*32 + n)*64 + t)*128) + dg*4));
    }
    if (tid < 32) {
        sm[OSB + tid]      = b1g[tid];
        sm[OSB + 32 + tid] = W2g[tid];
        sm[OSB + 64 + tid] = pmask[b*32 + tid] ? 1.f : 0.f;
        if (tid == 0) { sm[OSB+96] = physw[0]; sm[OSB+97] = priorw[0]; sm[OSB+98] = b2g[0]; }
    }
    if (tid >= 64 && tid < 192) {
        int i = tid - 64;
        sm[OSB + 128 + i] = W1[(i>>2)*260 + 256 + (i&3)];
    }
    __syncthreads();

    // ---------------- Phase 0b: Z -> bf16 hi/lo (OSCR; lives until content) ----------------
    cvt_split(sm + OZ, sm + OSCR, tid);
    __syncthreads();

    // ---------------- Phase 1: C1 = Z @ P -> OC (fp32) ----------------
    gemm_mma(sm + OSCR, g_Pbh, g_Pbl, sm + OC, nullptr, tid);

    // ---------------- Phase 4-mma: H = Z @ gU (A = Zbf; frags held in regs) ----------------
    float hc[2][4];
    {
        const int mw = warp & 1, ntg = warp >> 1;
        const int m = mw*16 + (lane & 7) + ((lane >> 3) & 1)*8;
        const int kbh = lane >> 4;
        const u32 base = (u32)__cvta_generic_to_shared(sm + OSCR);
#pragma unroll
        for (int nt = 0; nt < 2; nt++){ hc[nt][0]=0.f; hc[nt][1]=0.f; hc[nt][2]=0.f; hc[nt][3]=0.f; }
#pragma unroll
        for (int ks = 0; ks < 8; ks++){
            const int kb = ks*2 + kbh;
            const u32 off = (u32)(m*256 + ((kb ^ (m & 7)) << 4));
            u32 ah[4], al[4];
            ldsm4(ah, base + off);
            ldsm4(al, base + 8192 + off);
            const u32* bhp = g_Ubh + ((ks*8 + ntg*2)*32 + lane)*2;
            const u32* blp = g_Ubl + ((ks*8 + ntg*2)*32 + lane)*2;
#pragma unroll
            for (int nt = 0; nt < 2; nt++){
                uint2 bh = *reinterpret_cast<const uint2*>(bhp + nt*64);
                uint2 bl = *reinterpret_cast<const uint2*>(blp + nt*64);
                mma16816(hc[nt], ah, bh.x, bh.y);
                mma16816(hc[nt], ah, bl.x, bl.y);
                mma16816(hc[nt], al, bh.x, bh.y);
            }
        }
    }
    __syncthreads();   // C1 (OC) visible everywhere

    // ---------------- Phase 2-cvt: C1 -> bf16 hi/lo in place (OC) ----------------
    cvt_split_inplace(sm + OC, tid);
    __syncthreads();

    // ---------------- Phase 2-mma: content = C1bf @ Zbf^T -> LOG ----------------
    {
        const int mw = warp & 1, ng = warp >> 1;          // D tile: rows(n) mw*16, cols(m) ng*8
        const int m = mw*16 + (lane & 7) + ((lane >> 3) & 1)*8;
        const int kbh = lane >> 4;
        const u32 abase = (u32)__cvta_generic_to_shared(sm + OC);
        const u32 bbase = (u32)__cvta_generic_to_shared(sm + OSCR);
        const int brow = ng*8 + (lane & 7);
        const int bsel = (lane >> 3) & 1;
        float c[4] = {0.f, 0.f, 0.f, 0.f};
#pragma unroll
        for (int ks = 0; ks < 8; ks++){
            const u32 aoff = (u32)(m*256 + (((ks*2 + kbh) ^ (m & 7)) << 4));
            u32 ah[4], al[4];
            ldsm4(ah, abase + aoff);
            ldsm4(al, abase + 8192 + aoff);
            const u32 boff = (u32)(brow*256 + (((ks*2 + bsel) ^ (brow & 7)) << 4));
            u32 bh[2], bl[2];
            ldsm2(bh, bbase + boff);
            ldsm2(bl, bbase + 8192 + boff);
            mma16816(c, ah, bh[0], bh[1]);
            mma16816(c, ah, bl[0], bl[1]);
            mma16816(c, al, bh[0], bh[1]);
        }
        const int r0 = mw*16 + (lane >> 2), cb = ng*8 + (lane & 3)*2;
        *reinterpret_cast<float2*>(sm + OW + r0*36 + cb)     = make_float2(c[0], c[1]);
        *reinterpret_cast<float2*>(sm + OW + (r0+8)*36 + cb) = make_float2(c[2], c[3]);
    }
    __syncthreads();   // content-mma reads of OC/OSCR done -> OC free for HQ/HKT

    // ---------------- Phase 4-store: H frags -> HQ[32][36]@OC, HKT[32][33]@OC+1152 ----------------
    {
        const int mw = warp & 1, ntg = warp >> 1;
#pragma unroll
        for (int nt = 0; nt < 2; nt++) {
#pragma unroll
            for (int i = 0; i < 4; i++) {
                int row = mw*16 + (lane >> 2) + ((i >> 1) & 1)*8;
                int j   = ntg*16 + nt*8 + (lane & 3)*2 + (i & 1);
                float v = hc[nt][i];
                if (j < 32) sm[OC + row*36 + j] = v;
                else        sm[OC + 1152 + (j-32)*33 + row] = v;
            }
        }
    }

    // ---------------- Prefetch edge / prior ----------------
    const int pn = tid >> 3, pm0 = (tid & 7) << 2;
    float4 e4[4]; float lpr[4];
    {
        const float wf0 = __ldg(Wfuse+0), wf1 = __ldg(Wfuse+1), wf2 = __ldg(Wfuse+2),
                    wf3 = __ldg(Wfuse+3), wf4 = __ldg(Wfuse+4);
#pragma unroll
        for (int mm = 0; mm < 4; mm++) {
            size_t pair = (size_t)bt*1024 + pn*32 + pm0 + mm;
            e4[mm] = ld4(edge + pair*4);
            const float* ap = Aprior + pair*5;
            float p = ap[0]*wf0 + ap[1]*wf1 + ap[2]*wf2 + ap[3]*wf3 + ap[4]*wf4;
            if (!isfinite(p)) p = 0.f;
            p = fmaxf(p, 0.f);
            lpr[mm] = logf(p + 1e-6f);
        }
    }
    __syncthreads();

    // ---------------- Phase 5: phys MLP + prior + logits ----------------
    {
        float ph[4] = {0.f, 0.f, 0.f, 0.f};
#pragma unroll
        for (int j = 0; j < 32; j += 4) {
            float4 hqv = ld4(sm + OC + pn*36 + j);
            float4 b1v = ld4(sm + OSB + j);
            float4 w2v = ld4(sm + OSB + 32 + j);
            float hq4[4] = {hqv.x, hqv.y, hqv.z, hqv.w};
            float b14[4] = {b1v.x, b1v.y, b1v.z, b1v.w};
            float w24[4] = {w2v.x, w2v.y, w2v.z, w2v.w};
#pragma unroll
            for (int jj = 0; jj < 4; jj++) {
                int jc = j + jj;
                float hqb = hq4[jj] + b14[jj];
                float w2s = w24[jj];
                float4 we = ld4(sm + OSB + 128 + jc*4);
#pragma unroll
                for (int mm = 0; mm < 4; mm++) {
                    float h = hqb + sm[OC + 1152 + jc*33 + pm0 + mm]
                            + e4[mm].x*we.x + e4[mm].y*we.y
                            + e4[mm].z*we.z + e4[mm].w*we.w;
                    h = fmaxf(h, 0.f);
                    ph[mm] = fmaf(h, w2s, ph[mm]);
                }
            }
        }
        float pw = sm[OSB+96], prw = sm[OSB+97], b2v = sm[OSB+98];
        float mn = sm[OSB + 64 + pn];
#pragma unroll
        for (int mm = 0; mm < 4; mm++) {
            float lg = sm[OW + pn*36 + pm0 + mm]
                     + pw * (ph[mm] + b2v)
                     + prw * lpr[mm];
            if (mn != 0.f || sm[OSB + 64 + pm0 + mm] != 0.f) lg = -1e9f;
            sm[OW + pn*36 + pm0 + mm] = lg;
        }
    }
    __syncthreads();

    // ---------------- Phase 6: softmax (warp per 4 rows) ----------------
#pragma unroll
    for (int q = 0; q < 4; q++) {
        int n = warp*4 + q;
        float v = sm[OW + n*36 + lane];
        float mx = v;
#pragma unroll
        for (int off = 16; off > 0; off >>= 1)
            mx = fmaxf(mx, __shfl_xor_sync(0xffffffffu, mx, off));
        float e = expf(v - mx);
        float s = e;
#pragma unroll
        for (int off = 16; off > 0; off >>= 1)
            s += __shfl_xor_sync(0xffffffffu, s, off);
        sm[OW + n*36 + lane] = e / s;
    }
    __syncthreads();

    // ---------------- Phase 7: AZ = alpha @ Z -> OC (HQ/HKT dead) ----------------
    {
        const int r0 = warp * 4;
        const int c0 = lane * 4;
        u64 acc[8];
#pragma unroll
        for (int i = 0; i < 8; i++) acc[i] = 0ull;
#pragma unroll 2
        for (int k = 0; k < 32; k += 4) {
            float4 a[4];
#pragma unroll
            for (int i = 0; i < 4; i++) a[i] = ld4(sm + OW + (r0 + i)*36 + k);
#pragma unroll
            for (int u = 0; u < 4; u++) {
                ulonglong2 zv = ldp2(sm + OZ + (k+u)*136 + c0);
#pragma unroll
                for (int i = 0; i < 4; i++) {
                    float av = (u==0) ? a[i].x : (u==1) ? a[i].y : (u==2) ? a[i].z : a[i].w;
                    u64 ad = pk2(av, av);
                    acc[i*2]   = fma2(ad, zv.x, acc[i*2]);
                    acc[i*2+1] = fma2(ad, zv.y, acc[i*2+1]);
                }
            }
        }
#pragma unroll
        for (int i = 0; i < 4; i++)
            stp2(sm + OC + (r0+i)*136 + c0, acc[i*2], acc[i*2+1]);
    }
    __syncthreads();

    // ---------------- Phase 7b: AZ -> bf16 hi/lo (OSCR, over Zbf) ----------------
    cvt_split(sm + OC, sm + OSCR, tid);
    __syncthreads();

    // ---------------- Phase 8: y = Z + AZ @ G -> OC (bf16 3-split mma) ----------------
    gemm_mma(sm + OSCR, g_Gbh, g_Gbl, sm + OC, sm + OZ, tid);
    __syncthreads();

    // ---------------- Phase 9: LayerNorm + masked store ----------------
    {
        float4 gv = __ldg(reinterpret_cast<const float4*>(gammag + lane*4));
        float4 bv = __ldg(reinterpret_cast<const float4*>(betag + lane*4));
#pragma unroll
        for (int q = 0; q < 4; q++) {
            int n = warp*4 + q;
            float4 y = ld4(sm + OC + n*136 + lane*4);
            float s  = y.x + y.y + y.z + y.w;
            float s2 = y.x*y.x + y.y*y.y + y.z*y.z + y.w*y.w;
#pragma unroll
            for (int off = 16; off > 0; off >>= 1) {
                s  += __shfl_xor_sync(0xffffffffu, s, off);
                s2 += __shfl_xor_sync(0xffffffffu, s2, off);
            }
            float mu   = s * (1.f/128.f);
            float var  = s2 * (1.f/128.f) - mu*mu;
            float rstd = rsqrtf(var + 1e-5f);
            float4 o;
            o.x = (y.x - mu)*rstd*gv.x + bv.x;
            o.y = (y.y - mu)*rstd*gv.y + bv.y;
            o.z = (y.z - mu)*rstd*gv.z + bv.z;
            o.w = (y.w - mu)*rstd*gv.w + bv.w;
            if (sm[OSB + 64 + n] != 0.f) o = make_float4(0.f, 0.f, 0.f, 0.f);
            reinterpret_cast<float4*>(out)[(((size_t)b*32 + n)*64 + t)*32 + lane] = o;
        }
    }
}

extern "C" void kernel_launch(void* const* d_in, const int* in_sizes, int n_in,
                              void* d_out, int out_size) {
    (void)in_sizes; (void)n_in; (void)out_size;
    const float* x      = (const float*)d_in[0];
    const float* edge   = (const float*)d_in[1];
    const float* Aprior = (const float*)d_in[2];
    const unsigned char* pmask = (const unsigned char*)d_in[3];
    const float* Wq     = (const float*)d_in[4];
    const float* Wk     = (const float*)d_in[5];
    const float* Wv     = (const float*)d_in[6];
    const float* Th     = (const float*)d_in[7];
    const float* Wfuse  = (const float*)d_in[8];
    const float* W1     = (const float*)d_in[9];
    const float* b1     = (const float*)d_in[10];
    const float* W2     = (const float*)d_in[11];
    const float* b2     = (const float*)d_in[12];
    const float* gamma  = (const float*)d_in[13];
    const float* beta   = (const float*)d_in[14];
    const float* physw  = (const float*)d_in[15];
    const float* priorw = (const float*)d_in[16];
    float* out = (float*)d_out;

    prep_kernel<<<192, 128>>>(Wq, Wk, Wv, Th, W1);

    cudaFuncSetAttribute(fused_gnn_kernel,
                         cudaFuncAttributeMaxDynamicSharedMemorySize, SMEMF * 4);
    fused_gnn_kernel<<<512, TPB, SMEMF * 4>>>(x, edge, Aprior, pmask, Wfuse, W1, b1, W2, b2,
                                              gamma, beta, physw, priorw, out);
}